// round 13
// baseline (speedup 1.0000x reference)
#include <cuda_runtime.h>

#define ROWS  144
#define NCOLS 576
#define DEG   6
#define ITER  3
#define TPB   288   // 2 threads per row; one batch element per block

// Sparse structure of H + quantizer constants (written by prep_kernel).
__device__ int   g_cols[ROWS * DEG];
__device__ float g_q[ITER][11];

__device__ __forceinline__ float ex2f(float x) {
    float y;
    asm("ex2.approx.ftz.f32 %0, %1;" : "=f"(y) : "f"(x));
    return y;
}

// One block per row, 576 threads: coalesced read + ballot-based ordered rank.
// Block 0 / threads 0..2 also compute the quantizer constants. Each block
// fires the PDL trigger as soon as its work is done.
__global__ void prep_kernel(const float* __restrict__ H,
                            const float* __restrict__ eta,
                            const float* __restrict__ qk)
{
    __shared__ int wcnt[18];
    __shared__ int wpre[18];
    const int row  = blockIdx.x;
    const int j    = threadIdx.x;          // 0..575
    const int w    = j >> 5, lane = j & 31;
    const float v  = H[row * NCOLS + j];
    const unsigned mask = __ballot_sync(0xffffffffu, v != 0.0f);
    if (lane == 0) wcnt[w] = __popc(mask);
    __syncthreads();
    if (j == 0) {
        int s = 0;
        #pragma unroll
        for (int k = 0; k < 18; ++k) { wpre[k] = s; s += wcnt[k]; }
    }
    __syncthreads();
    if (v != 0.0f) {
        int rank = wpre[w] + __popc(mask & ((1u << lane) - 1u));
        if (rank < DEG) g_cols[row * DEG + rank] = j;
    }

    if (row == 0 && j < ITER) {            // one thread per iteration t
        const float q0 = qk[0], q1 = qk[1], q2 = qk[2], q3 = qk[3];
        const float dq = (q3 - q0) * (1.0f / 3.0f);
        const int t = j;
        float et  = eta[t];
        float c   = 1.0f / (2.0f * et * et + 1e-12f);
        float lam = 2.0f * c * dq;
        float k0 = __expf(-c * q0 * q0), k1 = __expf(-c * q1 * q1);
        float k2 = __expf(-c * q2 * q2), k3 = __expf(-c * q3 * q3);
        g_q[t][0] = -lam * 1.44269504f;    // fold log2(e) for ex2
        g_q[t][1] = k0; g_q[t][2] = k1; g_q[t][3] = k2; g_q[t][4] = k3;
        g_q[t][5] = k0 * q0; g_q[t][6] = k1 * q1;
        g_q[t][7] = k2 * q2; g_q[t][8] = k3 * q3;
        float den = (k0 + k1) + (k2 + k3);
        float num = (k0 * q0 + k1 * q1) + (k2 * q2 + k3 * q3);
        float qz0 = num / den;             // quantize(0)
        g_q[t][9]  = qz0;
        g_q[t][10] = (float)ROWS * qz0;
    }

    __syncthreads();
    if (j == 0) cudaTriggerProgrammaticLaunchCompletion();
}

__global__ __launch_bounds__(TPB) void decode_kernel(
    const float* __restrict__ r,
    const float* __restrict__ alpha,
    const float* __restrict__ beta,
    float* __restrict__ out)
{
    __shared__ float sr[NCOLS];         // r for this batch element
    __shared__ float sc[2][NCOLS];      // double-buffered column sums

    const int tid  = threadIdx.x;
    const int b    = blockIdx.x;
    const int row  = tid >> 1;          // 0..143
    const int half = tid & 1;           // which 3 edges of the row

    // Prelude overlapping the prep grid: load r before the dependency wait.
    const float2 sv = ((const float2*)(r + (size_t)b * NCOLS))[tid];
    ((float2*)sr)[tid] = sv;

    // Wait for prep_kernel's memory (PDL edge) — then its writes are visible.
    cudaGridDependencySynchronize();

    int ci[3];
    #pragma unroll
    for (int k = 0; k < 3; ++k) ci[k] = g_cols[row * DEG + half * 3 + k];
    __syncthreads();                    // sr stores visible block-wide

    unsigned sb[3];
    float rv[3], M[3], E[3];
    #pragma unroll
    for (int k = 0; k < 3; ++k) { rv[k] = sr[ci[k]]; M[k] = rv[k]; }

    #pragma unroll
    for (int t = 0; t < ITER; ++t) {
        const float nlam2 = g_q[t][0];
        const float k0 = g_q[t][1], k1 = g_q[t][2];
        const float k2 = g_q[t][3], k3 = g_q[t][4];
        const float kq0 = g_q[t][5], kq1 = g_q[t][6];
        const float kq2 = g_q[t][7], kq3 = g_q[t][8];
        const float qz0  = g_q[t][9];
        const float init = g_q[t][10];
        const float a  = alpha[t];
        const float bt = beta[t];

        // Geometric-weight soft quantizer; magnitude form (x >= 0).
        auto qmag = [&](float x) -> float {
            float v = ex2f(nlam2 * x), v2 = v * v, v3 = v2 * v;
            float den = fmaf(v3, k0,  fmaf(v2, k1,  fmaf(v, k2,  k3)));
            float num = fmaf(v3, kq0, fmaf(v2, kq1, fmaf(v, kq2, kq3)));
            return __fdividef(num, den);
        };
        // Signed form via odd symmetry (qk symmetric: k0=k3, k1=k2).
        auto qsgn = [&](float x) -> float {
            float ax = fabsf(x);
            float v = ex2f(nlam2 * ax), v2 = v * v, v3 = v2 * v;
            float den = fmaf(v3, k0,  fmaf(v2, k1,  fmaf(v, k2,  k3)));
            float num = fmaf(v3, kq0, fmaf(v2, kq1, fmaf(v, kq2, kq3)));
            return copysignf(__fdividef(num, den), x);
        };

        // Init column sums: sum_E[j] = 144*qz0 + sum_{support}(E - qz0)
        float* cs = sc[t & 1];
        ((float2*)cs)[tid] = make_float2(init, init);

        // ---- Row stats, packed-key form. |M| >= 0 so float order == uint
        //      order; low 3 bits of key carry the edge id (gives the
        //      reference's lowest-index tie-break automatically). ----
        unsigned u1 = 0xffffffffu, u2 = 0xffffffffu, par = 0u, az = 0u;
        #pragma unroll
        for (int k = 0; k < 3; ++k) {
            unsigned mb = __float_as_uint(M[k]);
            unsigned am = mb & 0x7fffffffu;
            sb[k] = mb & 0x80000000u;
            par ^= mb >> 31;
            az  |= (am == 0u);
            unsigned key = (am & ~7u) | (unsigned)(half * 3 + k);
            unsigned hi = umax(u1, key);
            u1 = umin(u1, key);
            u2 = umin(u2, hi);
        }
        // Pack (min2, zeroflag, parity); merge with partner: 2 shuffles.
        unsigned p2  = (u2 & ~3u) | (az << 1) | par;
        unsigned ok1 = __shfl_xor_sync(0xffffffffu, u1, 1);
        unsigned op2 = __shfl_xor_sync(0xffffffffu, p2, 1);
        par = (p2 ^ op2) & 1u;
        az  = ((p2 | op2) >> 1) & 1u;
        unsigned m1k = umin(u1, ok1);
        unsigned m2k = umin(umax(u1, ok1), umin(p2 & ~3u, op2 & ~3u));
        const unsigned id = m1k & 7u;
        const float m1f = __uint_as_float(m1k & ~7u);
        const float m2f = __uint_as_float(m2k & ~7u);

        // Two distinct E magnitudes per row; sign = rowparity XOR own sign.
        const float Q1 = qmag(a * fmaxf(0.0f, m1f - bt));
        const float Q2 = qmag(a * fmaxf(0.0f, m2f - bt));
        const unsigned pb = par << 31;
        #pragma unroll
        for (int k = 0; k < 3; ++k) {
            float Qs = ((unsigned)(half * 3 + k) == id) ? Q2 : Q1;
            unsigned eb = __float_as_uint(Qs) ^ pb ^ sb[k];
            E[k] = az ? qz0 : __uint_as_float(eb);  // any zero sign -> quant(0)
        }
        __syncthreads();   // cs init visible; prior-iter cs readers done
        #pragma unroll
        for (int k = 0; k < 3; ++k) atomicAdd(&cs[ci[k]], E[k] - qz0);
        __syncthreads();   // column sums complete
        if (t + 1 < ITER) {
            #pragma unroll
            for (int k = 0; k < 3; ++k)
                M[k] = qsgn(rv[k] + cs[ci[k]] - E[k]);
        }
    }

    const float* csf = sc[(ITER - 1) & 1];
    const float2 cv = ((const float2*)csf)[tid];
    ((float2*)(out + (size_t)b * NCOLS))[tid] =
        make_float2(sv.x + cv.x, sv.y + cv.y);
}

extern "C" void kernel_launch(void* const* d_in, const int* in_sizes, int n_in,
                              void* d_out, int out_size)
{
    const float* r     = (const float*)d_in[0];
    const float* H     = (const float*)d_in[1];
    const float* alpha = (const float*)d_in[2];
    const float* beta  = (const float*)d_in[3];
    const float* eta   = (const float*)d_in[4];
    const float* qk    = (const float*)d_in[5];
    float* out = (float*)d_out;

    const int batch = in_sizes[0] / NCOLS;   // 512

    // Primary: prep. Plain launch on the capture (legacy) stream.
    prep_kernel<<<ROWS, NCOLS>>>(H, eta, qk);

    // Secondary: decode, launched with a PDL edge so its prelude overlaps
    // prep's tail instead of waiting for a full grid-completion gap.
    {
        cudaLaunchConfig_t cfg = {};
        cfg.gridDim  = dim3((unsigned)batch, 1, 1);
        cfg.blockDim = dim3(TPB, 1, 1);
        cfg.dynamicSmemBytes = 0;
        cfg.stream = 0;   // same (legacy) stream the harness captures
        cudaLaunchAttribute attr;
        attr.id = cudaLaunchAttributeProgrammaticStreamSerialization;
        attr.val.programmaticStreamSerializationAllowed = 1;
        cfg.attrs = &attr;
        cfg.numAttrs = 1;
        cudaLaunchKernelEx(&cfg, decode_kernel, r, alpha, beta, out);
    }
}

// round 14
// speedup vs baseline: 1.0125x; 1.0125x over previous
#include <cuda_runtime.h>

#define ROWS  144
#define NCOLS 576
#define DEG   6
#define ITER  3
#define TPB   288   // 2 threads per row; one batch element per block

// Sparse structure of H + quantizer constants (written by prep_kernel).
__device__ int   g_cols[ROWS * DEG];
__device__ float g_q[ITER][11];

typedef unsigned long long u64;

__device__ __forceinline__ float ex2f(float x) {
    float y;
    asm("ex2.approx.ftz.f32 %0, %1;" : "=f"(y) : "f"(x));
    return y;
}
// Packed fp32x2 helpers (Blackwell: fma.rn.f32x2 reachable only via PTX).
__device__ __forceinline__ u64 pk2(float lo, float hi) {
    u64 r; asm("mov.b64 %0, {%1, %2};" : "=l"(r) : "f"(lo), "f"(hi)); return r;
}
__device__ __forceinline__ void unpk2(u64 p, float& lo, float& hi) {
    asm("mov.b64 {%0, %1}, %2;" : "=f"(lo), "=f"(hi) : "l"(p));
}
__device__ __forceinline__ u64 fma2_(u64 a, u64 b, u64 c) {
    u64 d; asm("fma.rn.f32x2 %0, %1, %2, %3;" : "=l"(d) : "l"(a), "l"(b), "l"(c));
    return d;
}
__device__ __forceinline__ u64 mul2_(u64 a, u64 b) {
    u64 d; asm("mul.rn.f32x2 %0, %1, %2;" : "=l"(d) : "l"(a), "l"(b));
    return d;
}

// One block per row, 576 threads: coalesced read + ballot-based ordered rank.
// Block 0 / threads 0..2 also compute the quantizer constants.
__global__ void prep_kernel(const float* __restrict__ H,
                            const float* __restrict__ eta,
                            const float* __restrict__ qk)
{
    __shared__ int wcnt[18];
    __shared__ int wpre[18];
    const int row  = blockIdx.x;
    const int j    = threadIdx.x;          // 0..575
    const int w    = j >> 5, lane = j & 31;
    const float v  = H[row * NCOLS + j];
    const unsigned mask = __ballot_sync(0xffffffffu, v != 0.0f);
    if (lane == 0) wcnt[w] = __popc(mask);
    __syncthreads();
    if (j == 0) {
        int s = 0;
        #pragma unroll
        for (int k = 0; k < 18; ++k) { wpre[k] = s; s += wcnt[k]; }
    }
    __syncthreads();
    if (v != 0.0f) {
        int rank = wpre[w] + __popc(mask & ((1u << lane) - 1u));
        if (rank < DEG) g_cols[row * DEG + rank] = j;
    }

    if (row == 0 && j < ITER) {            // one thread per iteration t
        const float q0 = qk[0], q1 = qk[1], q2 = qk[2], q3 = qk[3];
        const float dq = (q3 - q0) * (1.0f / 3.0f);
        const int t = j;
        float et  = eta[t];
        float c   = 1.0f / (2.0f * et * et + 1e-12f);
        float lam = 2.0f * c * dq;
        float k0 = __expf(-c * q0 * q0), k1 = __expf(-c * q1 * q1);
        float k2 = __expf(-c * q2 * q2), k3 = __expf(-c * q3 * q3);
        g_q[t][0] = -lam * 1.44269504f;    // fold log2(e) for ex2
        g_q[t][1] = k0; g_q[t][2] = k1; g_q[t][3] = k2; g_q[t][4] = k3;
        g_q[t][5] = k0 * q0; g_q[t][6] = k1 * q1;
        g_q[t][7] = k2 * q2; g_q[t][8] = k3 * q3;
        float den = (k0 + k1) + (k2 + k3);
        float num = (k0 * q0 + k1 * q1) + (k2 * q2 + k3 * q3);
        float qz0 = num / den;             // quantize(0)
        g_q[t][9]  = qz0;
        g_q[t][10] = (float)ROWS * qz0;
    }
}

__global__ __launch_bounds__(TPB) void decode_kernel(
    const float* __restrict__ r,
    const float* __restrict__ alpha,
    const float* __restrict__ beta,
    float* __restrict__ out)
{
    __shared__ float sr[NCOLS];         // r for this batch element
    __shared__ float sc[2][NCOLS];      // double-buffered column sums
    __shared__ float s_q[ITER][13];     // staged constants: g_q + alpha + beta

    const int tid  = threadIdx.x;
    const int b    = blockIdx.x;
    const int row  = tid >> 1;          // 0..143
    const int half = tid & 1;           // which 3 edges of the row

    // Prelude: load r + stage all per-iteration constants into shared once,
    // taking the LDG latency off the per-iteration critical path.
    const float2 sv = ((const float2*)(r + (size_t)b * NCOLS))[tid];
    ((float2*)sr)[tid] = sv;
    if (tid < ITER * 13) {
        const int t = tid / 13, i = tid - t * 13;
        s_q[t][i] = (i < 11) ? g_q[t][i] : ((i == 11) ? alpha[t] : beta[t]);
    }

    int ci[3];
    #pragma unroll
    for (int k = 0; k < 3; ++k) ci[k] = g_cols[row * DEG + half * 3 + k];
    __syncthreads();                    // sr + s_q visible block-wide

    unsigned sb[3];
    float rv[3], M[3], E[3];
    #pragma unroll
    for (int k = 0; k < 3; ++k) { rv[k] = sr[ci[k]]; M[k] = rv[k]; }

    #pragma unroll
    for (int t = 0; t < ITER; ++t) {
        const float nlam2 = s_q[t][0];
        const float k0 = s_q[t][1], k1 = s_q[t][2];
        const float k2 = s_q[t][3], k3 = s_q[t][4];
        const float qz0  = s_q[t][9];
        const float init = s_q[t][10];
        const float a  = s_q[t][11];
        const float bt = s_q[t][12];
        // Broadcast-packed constants for the f32x2 polynomial chains.
        const u64 K0p  = pk2(k0, k0),  K1p  = pk2(k1, k1);
        const u64 K2p  = pk2(k2, k2),  K3p  = pk2(k3, k3);
        const u64 KQ0p = pk2(s_q[t][5], s_q[t][5]);
        const u64 KQ1p = pk2(s_q[t][6], s_q[t][6]);
        const u64 KQ2p = pk2(s_q[t][7], s_q[t][7]);
        const u64 KQ3p = pk2(s_q[t][8], s_q[t][8]);

        // Packed pair quantizer on magnitudes (x >= 0): geometric weights,
        // w_i ∝ k_i v^(3-i), v = 2^(nlam2*x) <= 1 (overflow-safe).
        auto qmag2 = [&](float x0, float x1, float& r0, float& r1) {
            float va = ex2f(nlam2 * x0);
            float vb = ex2f(nlam2 * x1);
            u64 V  = pk2(va, vb);
            u64 V2 = mul2_(V, V);
            u64 V3 = mul2_(V2, V);
            u64 DEN = fma2_(V3, K0p,  fma2_(V2, K1p,  fma2_(V, K2p,  K3p)));
            u64 NUM = fma2_(V3, KQ0p, fma2_(V2, KQ1p, fma2_(V, KQ2p, KQ3p)));
            float d0, d1, n0, n1;
            unpk2(DEN, d0, d1); unpk2(NUM, n0, n1);
            r0 = __fdividef(n0, d0);
            r1 = __fdividef(n1, d1);
        };
        // Scalar signed quant (odd symmetry) for the odd one out.
        auto qsgn = [&](float x) -> float {
            float ax = fabsf(x);
            float v = ex2f(nlam2 * ax), v2 = v * v, v3 = v2 * v;
            float den = fmaf(v3, k0, fmaf(v2, k1, fmaf(v, k2, k3)));
            float num = fmaf(v3, s_q[t][5],
                        fmaf(v2, s_q[t][6], fmaf(v, s_q[t][7], s_q[t][8])));
            return copysignf(__fdividef(num, den), x);
        };

        // Init column sums: sum_E[j] = 144*qz0 + sum_{support}(E - qz0)
        float* cs = sc[t & 1];
        ((float2*)cs)[tid] = make_float2(init, init);

        // ---- Row stats, packed-key form. |M| >= 0 so float order == uint
        //      order; low 3 bits carry edge id (lowest-index tie-break). ----
        unsigned u1 = 0xffffffffu, u2 = 0xffffffffu, par = 0u, az = 0u;
        #pragma unroll
        for (int k = 0; k < 3; ++k) {
            unsigned mb = __float_as_uint(M[k]);
            unsigned am = mb & 0x7fffffffu;
            sb[k] = mb & 0x80000000u;
            par ^= mb >> 31;
            az  |= (am == 0u);
            unsigned key = (am & ~7u) | (unsigned)(half * 3 + k);
            unsigned hi = umax(u1, key);
            u1 = umin(u1, key);
            u2 = umin(u2, hi);
        }
        // Pack (min2, zeroflag, parity); merge with partner: 2 shuffles.
        unsigned p2  = (u2 & ~3u) | (az << 1) | par;
        unsigned ok1 = __shfl_xor_sync(0xffffffffu, u1, 1);
        unsigned op2 = __shfl_xor_sync(0xffffffffu, p2, 1);
        par = (p2 ^ op2) & 1u;
        az  = ((p2 | op2) >> 1) & 1u;
        unsigned m1k = umin(u1, ok1);
        unsigned m2k = umin(umax(u1, ok1), umin(p2 & ~3u, op2 & ~3u));
        const unsigned id = m1k & 7u;
        const float m1f = __uint_as_float(m1k & ~7u);
        const float m2f = __uint_as_float(m2k & ~7u);

        // Two distinct E magnitudes per row -> one packed quant pair.
        float Q1, Q2;
        qmag2(a * fmaxf(0.0f, m1f - bt), a * fmaxf(0.0f, m2f - bt), Q1, Q2);
        const unsigned pb = par << 31;
        #pragma unroll
        for (int k = 0; k < 3; ++k) {
            float Qs = ((unsigned)(half * 3 + k) == id) ? Q2 : Q1;
            unsigned eb = __float_as_uint(Qs) ^ pb ^ sb[k];
            E[k] = az ? qz0 : __uint_as_float(eb);  // any zero sign -> quant(0)
        }
        __syncthreads();   // cs init visible; prior-iter cs readers done
        #pragma unroll
        for (int k = 0; k < 3; ++k) atomicAdd(&cs[ci[k]], E[k] - qz0);
        __syncthreads();   // column sums complete
        if (t + 1 < ITER) {
            // M-update: 3 signed quants -> one packed pair + one scalar.
            float x0 = rv[0] + cs[ci[0]] - E[0];
            float x1 = rv[1] + cs[ci[1]] - E[1];
            float x2 = rv[2] + cs[ci[2]] - E[2];
            float y0, y1;
            qmag2(fabsf(x0), fabsf(x1), y0, y1);
            M[0] = copysignf(y0, x0);
            M[1] = copysignf(y1, x1);
            M[2] = qsgn(x2);
        }
    }

    const float* csf = sc[(ITER - 1) & 1];
    const float2 cv = ((const float2*)csf)[tid];
    ((float2*)(out + (size_t)b * NCOLS))[tid] =
        make_float2(sv.x + cv.x, sv.y + cv.y);
}

extern "C" void kernel_launch(void* const* d_in, const int* in_sizes, int n_in,
                              void* d_out, int out_size)
{
    const float* r     = (const float*)d_in[0];
    const float* H     = (const float*)d_in[1];
    const float* alpha = (const float*)d_in[2];
    const float* beta  = (const float*)d_in[3];
    const float* eta   = (const float*)d_in[4];
    const float* qk    = (const float*)d_in[5];
    float* out = (float*)d_out;

    const int batch = in_sizes[0] / NCOLS;   // 512

    prep_kernel<<<ROWS, NCOLS>>>(H, eta, qk);
    decode_kernel<<<batch, TPB>>>(r, alpha, beta, out);
}